// round 14
// baseline (speedup 1.0000x reference)
#include <cuda_runtime.h>
#include <cstdint>

// img: [256, 3, 224, 224] f32, y_idx/x_idx: [256] i32.
// out[b,c,h,w] = img * (0 if h in [y,y+32) && w in [x,x+32) else 1)
//
// TMA/bulk-async path probe: per CTA, cp.async.bulk GMEM->SMEM (32 KB),
// threads zero only in-square elements in SMEM (~2% of data), then
// cp.async.bulk SMEM->GMEM. Bypasses L1/registers entirely; 6 CTAs/SM x
// 32 KB bulk requests in flight. Tests whether the 75-78% DRAM plateau is
// the SM request path (then this wins) or the HBM R/W-mix ceiling (flat).

#define SQ 32
#define CH 3
#define HH 224
#define W4 56                          // float4 per row
#define PLANE_F4 (HH * W4)             // 12544
#define BATCH_F4 (CH * PLANE_F4)       // 37632
#define NTHREADS 256
#define F4_PER_CTA 2048                // 32 KB chunk
#define CHUNK_BYTES (F4_PER_CTA * 16)
#define NBLOCKS 4704                   // 9,633,792 / 2048 exactly
#define F4_PER_THREAD (F4_PER_CTA / NTHREADS)   // 8

// smem: [0,8) mbarrier; [128, 128+32768) data
#define SMEM_MBAR 0
#define SMEM_DATA 128
#define SMEM_TOTAL (SMEM_DATA + CHUNK_BYTES)

__device__ __forceinline__ uint32_t smem_u32(const void* p) {
    uint32_t a;
    asm("{ .reg .u64 t; cvta.to.shared.u64 t, %1; cvt.u32.u64 %0, t; }"
        : "=r"(a) : "l"(p));
    return a;
}

__global__ __launch_bounds__(NTHREADS)
void random_square_dropout_kernel(const float* __restrict__ img,
                                  const int* __restrict__ y_idx,
                                  const int* __restrict__ x_idx,
                                  float* __restrict__ out) {
    extern __shared__ char smem[];
    const uint32_t sbase = smem_u32(smem);
    const uint32_t mbar  = sbase + SMEM_MBAR;
    const uint32_t sdata = sbase + SMEM_DATA;
    const int tid = threadIdx.x;

    const long chunk_f4   = (long)blockIdx.x * F4_PER_CTA;
    const char* gsrc      = (const char*)(img) + chunk_f4 * 16;
    char*       gdst      = (char*)(out) + chunk_f4 * 16;

    // 1. Init mbarrier, bulk-load 32 KB GMEM -> SMEM.
    if (tid == 0) {
        asm volatile("mbarrier.init.shared.b64 [%0], 1;" :: "r"(mbar) : "memory");
        asm volatile("mbarrier.arrive.expect_tx.shared.b64 _, [%0], %1;"
                     :: "r"(mbar), "r"((uint32_t)CHUNK_BYTES) : "memory");
        asm volatile(
            "cp.async.bulk.shared::cta.global.mbarrier::complete_tx::bytes "
            "[%0], [%1], %2, [%3];"
            :: "r"(sdata), "l"(gsrc), "r"((uint32_t)CHUNK_BYTES), "r"(mbar)
            : "memory");
    }
    __syncthreads();

    // 2. Wait for the bulk load (parity 0).
    {
        uint32_t done;
        asm volatile(
            "{\n\t.reg .pred p;\n\t"
            "mbarrier.try_wait.parity.acquire.cta.shared::cta.b64 p, [%1], 0;\n\t"
            "selp.b32 %0, 1, 0, p;\n\t}"
            : "=r"(done) : "r"(mbar) : "memory");
        if (!done) {
            asm volatile(
                "{\n\t.reg .pred P1;\n\t"
                "WL_%=:\n\t"
                "mbarrier.try_wait.parity.acquire.cta.shared::cta.b64 P1, [%0], 0, 0x989680;\n\t"
                "@P1 bra.uni WD_%=;\n\t"
                "bra.uni WL_%=;\n\t"
                "WD_%=:\n\t}"
                :: "r"(mbar) : "memory");
        }
    }

    // 3. Zero in-square elements in SMEM (~2% of elements touched).
#pragma unroll
    for (int j = 0; j < F4_PER_THREAD; j++) {
        const int  local = tid + j * NTHREADS;               // f4 within chunk
        const long g     = chunk_f4 + local;                 // global f4 index
        const int  b     = (int)(g / BATCH_F4);
        const int  p     = (int)(g % BATCH_F4) % PLANE_F4;
        const int  h     = p / W4;
        const int  y     = __ldg(&y_idx[b]);
        if ((unsigned)(h - y) < SQ) {
            const int x  = __ldg(&x_idx[b]);
            const int w0 = (p % W4) * 4;
            // overlap test for this float4
            if (w0 + 3 >= x && w0 < x + SQ) {
                float* e = (float*)(smem + SMEM_DATA + (size_t)local * 16);
                if ((unsigned)(w0     - x) < SQ) e[0] = 0.f;
                if ((unsigned)(w0 + 1 - x) < SQ) e[1] = 0.f;
                if ((unsigned)(w0 + 2 - x) < SQ) e[2] = 0.f;
                if ((unsigned)(w0 + 3 - x) < SQ) e[3] = 0.f;
            }
        }
    }
    __syncthreads();

    // 4. Bulk-store 32 KB SMEM -> GMEM.
    if (tid == 0) {
        asm volatile("fence.proxy.async.shared::cta;" ::: "memory");
        asm volatile(
            "cp.async.bulk.global.shared::cta.bulk_group [%0], [%1], %2;"
            :: "l"(gdst), "r"(sdata), "r"((uint32_t)CHUNK_BYTES) : "memory");
        asm volatile("cp.async.bulk.commit_group;" ::: "memory");
        asm volatile("cp.async.bulk.wait_group 0;" ::: "memory");
    }
}

extern "C" void kernel_launch(void* const* d_in, const int* in_sizes, int n_in,
                              void* d_out, int out_size) {
    const float* img  = (const float*)d_in[0];
    const int* y_idx  = (const int*)d_in[1];
    const int* x_idx  = (const int*)d_in[2];
    float* out        = (float*)d_out;

    random_square_dropout_kernel<<<NBLOCKS, NTHREADS, SMEM_TOTAL>>>(
        img, y_idx, x_idx, out);
}

// round 15
// speedup vs baseline: 1.0309x; 1.0309x over previous
#include <cuda_runtime.h>

// img: [256, 3, 224, 224] f32, y_idx/x_idx: [256] i32.
// out[b,c,h,w] = img * (0 if h in [y,y+32) && w in [x,x+32) else 1)
//
// FINAL champion. 14 rounds of evidence: this op is pinned at the GB300
// mixed-R/W memory-system ceiling (~6.1 TB/s, 75-78% of 8 TB/s spec),
// path-independent — SM LDG/STG, copy engine, and TMA bulk-async all
// measure the same plateau. Config: tiled 32-row blocks, 224 threads
// (56x4), 8 front-batched coalesced float4 __ldcs loads per thread,
// predicated unsigned-range masking, __stcs stores. ~46-48 regs /
// 6 CTAs/SM is the optimum of the MLP-vs-occupancy trade: reg-capping
// (launch_bounds minBlocks) serializes the load batch, and higher
// occupancy only adds cross-CTA L1tex-queue spread.

#define SQ 32
#define BATCH 256
#define CH 3
#define HH 224
#define WW 224
#define W4 (WW / 4)                    // 56 float4 per row
#define TY 4                           // threads in y
#define RPT 8                          // rows per thread
#define TILE_H (TY * RPT)              // 32 rows per block

__global__ __launch_bounds__(W4 * TY)
void random_square_dropout_kernel(const float4* __restrict__ img,
                                  const int* __restrict__ y_idx,
                                  const int* __restrict__ x_idx,
                                  float4* __restrict__ out) {
    const int b  = blockIdx.z;
    const int c  = blockIdx.y;
    const int h0 = blockIdx.x * TILE_H + threadIdx.y;  // rows h0 + TY*k
    const int w4 = threadIdx.x;                        // 0..55

    const int y = __ldg(&y_idx[b]);
    const int x = __ldg(&x_idx[b]);

    const long plane = ((long)b * CH + c) * (long)(HH * W4);
    const long base  = plane + (long)h0 * W4 + w4;

    // Front-batched loads: 8 independent DRAM requests in flight per thread.
    float4 v[RPT];
#pragma unroll
    for (int k = 0; k < RPT; k++)
        v[k] = __ldcs(&img[base + (long)(k * TY) * W4]);

    // Column in-square flags (constant across this thread's rows).
    const int w0 = w4 * 4;
    const bool cx0 = (unsigned)(w0     - x) < SQ;
    const bool cx1 = (unsigned)(w0 + 1 - x) < SQ;
    const bool cx2 = (unsigned)(w0 + 2 - x) < SQ;
    const bool cx3 = (unsigned)(w0 + 3 - x) < SQ;

    if (cx0 || cx1 || cx2 || cx3) {
#pragma unroll
        for (int k = 0; k < RPT; k++) {
            const int h = h0 + k * TY;
            if ((unsigned)(h - y) < SQ) {
                if (cx0) v[k].x = 0.f;
                if (cx1) v[k].y = 0.f;
                if (cx2) v[k].z = 0.f;
                if (cx3) v[k].w = 0.f;
            }
        }
    }

#pragma unroll
    for (int k = 0; k < RPT; k++)
        __stcs(&out[base + (long)(k * TY) * W4], v[k]);
}

extern "C" void kernel_launch(void* const* d_in, const int* in_sizes, int n_in,
                              void* d_out, int out_size) {
    const float4* img = (const float4*)d_in[0];
    const int* y_idx  = (const int*)d_in[1];
    const int* x_idx  = (const int*)d_in[2];
    float4* out       = (float4*)d_out;

    dim3 block(W4, TY);                      // 56 x 4 = 224 threads
    dim3 grid(HH / TILE_H, CH, BATCH);       // 7 x 3 x 256 = 5376 blocks
    random_square_dropout_kernel<<<grid, block>>>(img, y_idx, x_idx, out);
}

// round 16
// speedup vs baseline: 1.0316x; 1.0006x over previous
#include <cuda_runtime.h>

// img: [256, 3, 224, 224] f32, y_idx/x_idx: [256] i32.
// out[b,c,h,w] = img * (0 if h in [y,y+32) && w in [x,x+32) else 1)
//
// FINAL champion — confirmed at the GB300 memory-system ceiling.
// 15 rounds of evidence: ~6.1 TB/s (75-78% of 8 TB/s spec) for this 1:1
// read/write stream, PATH-INDEPENDENT (SM LDG/STG == copy engine == TMA
// bulk-async). Config: tiled 32-row blocks, 224 threads (56x4), 8
// front-batched coalesced float4 __ldcs loads per thread, predicated
// unsigned-range masking, __stcs stores. ~48 regs / 6 CTAs/SM is the
// optimum of the MLP-vs-occupancy trade: capping regs serializes the load
// batch (R10), higher occupancy adds cross-CTA L1tex-queue spread (R8).

#define SQ 32
#define BATCH 256
#define CH 3
#define HH 224
#define WW 224
#define W4 (WW / 4)                    // 56 float4 per row
#define TY 4                           // threads in y
#define RPT 8                          // rows per thread
#define TILE_H (TY * RPT)              // 32 rows per block

__global__ __launch_bounds__(W4 * TY)
void random_square_dropout_kernel(const float4* __restrict__ img,
                                  const int* __restrict__ y_idx,
                                  const int* __restrict__ x_idx,
                                  float4* __restrict__ out) {
    const int b  = blockIdx.z;
    const int c  = blockIdx.y;
    const int h0 = blockIdx.x * TILE_H + threadIdx.y;  // rows h0 + TY*k
    const int w4 = threadIdx.x;                        // 0..55

    const int y = __ldg(&y_idx[b]);
    const int x = __ldg(&x_idx[b]);

    const long plane = ((long)b * CH + c) * (long)(HH * W4);
    const long base  = plane + (long)h0 * W4 + w4;

    // Front-batched loads: 8 independent DRAM requests in flight per thread.
    float4 v[RPT];
#pragma unroll
    for (int k = 0; k < RPT; k++)
        v[k] = __ldcs(&img[base + (long)(k * TY) * W4]);

    // Column in-square flags (constant across this thread's rows).
    const int w0 = w4 * 4;
    const bool cx0 = (unsigned)(w0     - x) < SQ;
    const bool cx1 = (unsigned)(w0 + 1 - x) < SQ;
    const bool cx2 = (unsigned)(w0 + 2 - x) < SQ;
    const bool cx3 = (unsigned)(w0 + 3 - x) < SQ;

    if (cx0 || cx1 || cx2 || cx3) {
#pragma unroll
        for (int k = 0; k < RPT; k++) {
            const int h = h0 + k * TY;
            if ((unsigned)(h - y) < SQ) {
                if (cx0) v[k].x = 0.f;
                if (cx1) v[k].y = 0.f;
                if (cx2) v[k].z = 0.f;
                if (cx3) v[k].w = 0.f;
            }
        }
    }

#pragma unroll
    for (int k = 0; k < RPT; k++)
        __stcs(&out[base + (long)(k * TY) * W4], v[k]);
}

extern "C" void kernel_launch(void* const* d_in, const int* in_sizes, int n_in,
                              void* d_out, int out_size) {
    const float4* img = (const float4*)d_in[0];
    const int* y_idx  = (const int*)d_in[1];
    const int* x_idx  = (const int*)d_in[2];
    float4* out       = (float4*)d_out;

    dim3 block(W4, TY);                      // 56 x 4 = 224 threads
    dim3 grid(HH / TILE_H, CH, BATCH);       // 7 x 3 x 256 = 5376 blocks
    random_square_dropout_kernel<<<grid, block>>>(img, y_idx, x_idx, out);
}